// round 6
// baseline (speedup 1.0000x reference)
#include <cuda_runtime.h>
#include <cuda_bf16.h>
#include <cstdint>
#include <cstddef>

#define BATCH 64
#define CH    512
#define LSEQ  512
#define MAT   (CH * LSEQ)
#define NMAT  (BATCH * MAT)

// ---------------- scratch -----------------------------------------------------
__device__ float    g_Y[3ULL * NMAT];        // Q,K,VT pre-BN fp32
__device__ float    g_Wsc[NMAT];             // scores fp32
__device__ uint16_t g_bf[12ULL * NMAT];      // QH,QL,KH,KL,VH,VL,WH,WL,X0H,X0L,X1H,X1L
__device__ uint16_t g_wth[9ULL * MAT];
__device__ uint16_t g_wtl[9ULL * MAT];
__device__ float g_sum[3 * CH];
__device__ float g_sq[3 * CH];
__device__ float g_mean[3 * CH];
__device__ float g_rstd[3 * CH];

// ---------------- helpers ------------------------------------------------------
__device__ __forceinline__ uint32_t packbf(float a, float b) {
    __nv_bfloat162 t = __floats2bfloat162_rn(a, b);
    return *reinterpret_cast<uint32_t*>(&t);
}
__device__ __forceinline__ float bf16rt(float x) {
    return __bfloat162float(__float2bfloat16(x));
}

#define LDSM4(R, addr) \
    asm volatile("ldmatrix.sync.aligned.m8n8.x4.shared.b16 {%0,%1,%2,%3}, [%4];" \
        : "=r"((R)[0]), "=r"((R)[1]), "=r"((R)[2]), "=r"((R)[3]) : "r"(addr))

__device__ __forceinline__ void mma16816(float* d, const uint32_t* a,
                                         uint32_t b0, uint32_t b1) {
    asm volatile(
        "mma.sync.aligned.m16n8k16.row.col.f32.bf16.bf16.f32 "
        "{%0,%1,%2,%3}, {%4,%5,%6,%7}, {%8,%9}, {%0,%1,%2,%3};"
        : "+f"(d[0]), "+f"(d[1]), "+f"(d[2]), "+f"(d[3])
        : "r"(a[0]), "r"(a[1]), "r"(a[2]), "r"(a[3]), "r"(b0), "r"(b1));
}

#define CP16(dst, src) \
    asm volatile("cp.async.cg.shared.global [%0], [%1], 16;" :: "r"(dst), "l"(src))
#define CPCOMMIT() asm volatile("cp.async.commit_group;" ::: "memory")
#define CPWAIT1()  asm volatile("cp.async.wait_group 1;" ::: "memory")

// ---------------- GEMM (NT, bf16x3, pre-split operands) ------------------------
// D[m][n] = sum_k A[m][k]*B[n][k], 512^3 per batch, A/B as bf16 hi+lo.
// CTA tile 128x128, 4 warps of 64x64, K-chunk 32, 3-stage cp.async pipeline.
// OUT: 0=fp32, 1=fp32+bias+rowstats, 2=fp32+bias+colstats, 3=bf16 hi/lo split.
#define KC 32
#define TILE_B  8192                     // 128 rows x 64 B
#define STAGE_B 32768                    // 4 tiles
#define SMEM_DYN (3 * STAGE_B)           // 98304

template<int OUT>
__global__ __launch_bounds__(128, 2) void gemm_bf3(
    const uint16_t* __restrict__ Ah, const uint16_t* __restrict__ Al, int strideA,
    const uint16_t* __restrict__ Bh, const uint16_t* __restrict__ Bl, int strideB,
    float* __restrict__ Cf,
    uint16_t* __restrict__ Ch, uint16_t* __restrict__ Cl,
    const float* __restrict__ bias,
    float* __restrict__ sums, float* __restrict__ sqs)
{
    extern __shared__ uint8_t smraw[];
    const uint32_t smemu = (uint32_t)__cvta_generic_to_shared(smraw);
    const int tid  = threadIdx.x;
    const int lane = tid & 31, wid = tid >> 5;
    const int m0 = blockIdx.y * 128, n0 = blockIdx.x * 128, b = blockIdx.z;

    const size_t oa = (size_t)b * strideA;
    const size_t ob = (size_t)b * strideB;

    // ---- loader: thread covers 16B chunk (r0 = tid>>2, k0 = tid&3), x4 p-steps
    // id = tid + 128*p -> row advances by 32 per p; swizzle phase unchanged.
    const int r0 = tid >> 2, k0 = tid & 3;
    const uint32_t dst0 = (uint32_t)(r0 * 64 + ((k0 ^ ((r0 >> 1) & 3)) << 4));
    const char* aH0 = (const char*)(Ah + oa + (size_t)(m0 + r0) * 512 + k0 * 8);
    const char* aL0 = (const char*)(Al + oa + (size_t)(m0 + r0) * 512 + k0 * 8);
    const char* bH0 = (const char*)(Bh + ob + (size_t)(n0 + r0) * 512 + k0 * 8);
    const char* bL0 = (const char*)(Bl + ob + (size_t)(n0 + r0) * 512 + k0 * 8);

    auto issue = [&](int s, int c) {
        const uint32_t sb = smemu + (uint32_t)s * STAGE_B;
        const size_t o = (size_t)c * (KC * 2);
#pragma unroll
        for (int p = 0; p < 4; p++) {
            const uint32_t d = sb + dst0 + p * 2048;       // 32 rows * 64 B
            const size_t so = o + (size_t)p * 32768;       // 32 rows * 1024 B
            CP16(d,              aH0 + so);
            CP16(d + TILE_B,     aL0 + so);
            CP16(d + 2 * TILE_B, bH0 + so);
            CP16(d + 3 * TILE_B, bL0 + so);
        }
    };

    // ---- compute-side per-lane ldmatrix offsets
    const int mw = (wid & 1) * 64;
    const int nw = (wid >> 1) * 64;
    const int lrow = (lane & 7) + 8 * ((lane >> 3) & 1);
    const int lk16 = lane >> 4;
    uint32_t offA[4][2], offB[4][2];
#pragma unroll
    for (int fi = 0; fi < 4; fi++) {
        const int row = mw + fi * 16 + lrow;
        const uint32_t sw = (row >> 1) & 3;
        offA[fi][0] = (uint32_t)(row * 64 + (((0 + lk16) ^ sw) << 4));
        offA[fi][1] = (uint32_t)(row * 64 + (((2 + lk16) ^ sw) << 4));
    }
#pragma unroll
    for (int bj = 0; bj < 4; bj++) {
        const int row = nw + bj * 16 + lrow;
        const uint32_t sw = (row >> 1) & 3;
        offB[bj][0] = (uint32_t)(row * 64 + (((0 + lk16) ^ sw) << 4));
        offB[bj][1] = (uint32_t)(row * 64 + (((2 + lk16) ^ sw) << 4));
    }

    float acc[4][8][4];
#pragma unroll
    for (int i = 0; i < 4; i++)
#pragma unroll
        for (int j = 0; j < 8; j++)
#pragma unroll
            for (int e = 0; e < 4; e++) acc[i][j][e] = 0.f;

    auto compute = [&](int s) {
        const uint32_t sb = smemu + (uint32_t)s * STAGE_B;
#pragma unroll
        for (int kg = 0; kg < 2; kg++) {
            uint32_t Ahr[4][4], Bhr[4][4], Blr[4][4], Alr[4][4];
#pragma unroll
            for (int fi = 0; fi < 4; fi++)
                LDSM4(Ahr[fi], sb + offA[fi][kg]);
#pragma unroll
            for (int bj = 0; bj < 4; bj++)
                LDSM4(Bhr[bj], sb + 2 * TILE_B + offB[bj][kg]);
#pragma unroll
            for (int i = 0; i < 4; i++)
#pragma unroll
                for (int j = 0; j < 8; j++)
                    mma16816(acc[i][j], Ahr[i], Bhr[j >> 1][j & 1], Bhr[j >> 1][(j & 1) + 2]);
#pragma unroll
            for (int bj = 0; bj < 4; bj++)
                LDSM4(Blr[bj], sb + 3 * TILE_B + offB[bj][kg]);
#pragma unroll
            for (int i = 0; i < 4; i++)
#pragma unroll
                for (int j = 0; j < 8; j++)
                    mma16816(acc[i][j], Ahr[i], Blr[j >> 1][j & 1], Blr[j >> 1][(j & 1) + 2]);
#pragma unroll
            for (int fi = 0; fi < 4; fi++)
                LDSM4(Alr[fi], sb + TILE_B + offA[fi][kg]);
#pragma unroll
            for (int i = 0; i < 4; i++)
#pragma unroll
                for (int j = 0; j < 8; j++)
                    mma16816(acc[i][j], Alr[i], Bhr[j >> 1][j & 1], Bhr[j >> 1][(j & 1) + 2]);
        }
    };

    issue(0, 0); CPCOMMIT();
    issue(1, 1); CPCOMMIT();

#pragma unroll 1
    for (int c = 0; c < 16; c++) {
        CPWAIT1();
        __syncthreads();
        if (c + 2 < 16) issue((c + 2) % 3, c + 2);
        CPCOMMIT();
        compute(c % 3);
    }

    // ---------------- epilogue ----------------
    const int rg = lane >> 2;
    const int cg = (lane & 3) * 2;
    float* CfB = Cf + (size_t)b * MAT;

    float bc[16];
    if (OUT == 2) {
#pragma unroll
        for (int j = 0; j < 8; j++) {
            bc[2 * j]     = bias[n0 + nw + j * 8 + cg];
            bc[2 * j + 1] = bias[n0 + nw + j * 8 + cg + 1];
        }
    }
    float cs[16], cq[16];
    if (OUT == 2) {
#pragma unroll
        for (int e = 0; e < 16; e++) { cs[e] = 0.f; cq[e] = 0.f; }
    }

#pragma unroll
    for (int i = 0; i < 4; i++) {
        const int row0 = m0 + mw + i * 16 + rg;
        const int row1 = row0 + 8;
        float bv0 = 0.f, bv1 = 0.f;
        if (OUT == 1) { bv0 = bias[row0]; bv1 = bias[row1]; }
        float s0 = 0.f, q0 = 0.f, s1 = 0.f, q1 = 0.f;
#pragma unroll
        for (int j = 0; j < 8; j++) {
            float* cc = acc[i][j];
            if (OUT == 1) { cc[0] += bv0; cc[1] += bv0; cc[2] += bv1; cc[3] += bv1; }
            if (OUT == 2) {
                cc[0] += bc[2 * j]; cc[1] += bc[2 * j + 1];
                cc[2] += bc[2 * j]; cc[3] += bc[2 * j + 1];
            }
            const int col = n0 + nw + j * 8 + cg;
            if (OUT == 3) {
                uint32_t* H = (uint32_t*)(Ch + (size_t)b * MAT);
                uint32_t* L = (uint32_t*)(Cl + (size_t)b * MAT);
                const size_t i0 = ((size_t)row0 * 512 + col) >> 1;
                const size_t i1 = ((size_t)row1 * 512 + col) >> 1;
                H[i0] = packbf(cc[0], cc[1]);
                L[i0] = packbf(cc[0] - bf16rt(cc[0]), cc[1] - bf16rt(cc[1]));
                H[i1] = packbf(cc[2], cc[3]);
                L[i1] = packbf(cc[2] - bf16rt(cc[2]), cc[3] - bf16rt(cc[3]));
            } else {
                *(float2*)&CfB[(size_t)row0 * 512 + col] = make_float2(cc[0], cc[1]);
                *(float2*)&CfB[(size_t)row1 * 512 + col] = make_float2(cc[2], cc[3]);
            }
            if (OUT == 1) {
                s0 += cc[0] + cc[1]; q0 += cc[0] * cc[0] + cc[1] * cc[1];
                s1 += cc[2] + cc[3]; q1 += cc[2] * cc[2] + cc[3] * cc[3];
            }
            if (OUT == 2) {
                cs[2 * j]     += cc[0] + cc[2];
                cs[2 * j + 1] += cc[1] + cc[3];
                cq[2 * j]     += cc[0] * cc[0] + cc[2] * cc[2];
                cq[2 * j + 1] += cc[1] * cc[1] + cc[3] * cc[3];
            }
        }
        if (OUT == 1) {
#pragma unroll
            for (int off = 1; off <= 2; off <<= 1) {
                s0 += __shfl_xor_sync(0xffffffffu, s0, off);
                q0 += __shfl_xor_sync(0xffffffffu, q0, off);
                s1 += __shfl_xor_sync(0xffffffffu, s1, off);
                q1 += __shfl_xor_sync(0xffffffffu, q1, off);
            }
            if ((lane & 3) == 0) {
                atomicAdd(&sums[row0], s0); atomicAdd(&sqs[row0], q0);
                atomicAdd(&sums[row1], s1); atomicAdd(&sqs[row1], q1);
            }
        }
    }
    if (OUT == 2) {
#pragma unroll
        for (int e = 0; e < 16; e++) {
#pragma unroll
            for (int off = 4; off <= 16; off <<= 1) {
                cs[e] += __shfl_xor_sync(0xffffffffu, cs[e], off);
                cq[e] += __shfl_xor_sync(0xffffffffu, cq[e], off);
            }
        }
        if (rg == 0) {
#pragma unroll
            for (int j = 0; j < 8; j++) {
                const int col = n0 + nw + j * 8 + cg;
                atomicAdd(&sums[col], cs[2 * j]);         atomicAdd(&sqs[col], cq[2 * j]);
                atomicAdd(&sums[col + 1], cs[2 * j + 1]); atomicAdd(&sqs[col + 1], cq[2 * j + 1]);
            }
        }
    }
}

// ---------------- elementwise kernels -------------------------------------------
__global__ void transpose_split(const float* __restrict__ src,
                                uint16_t* __restrict__ H, uint16_t* __restrict__ L)
{
    __shared__ float t[32][33];
    const int b = blockIdx.z;
    const int x0 = blockIdx.x * 32;
    const int y0 = blockIdx.y * 32;
    const float* S = src + (size_t)b * MAT;
    const int tx = threadIdx.x, ty = threadIdx.y;
#pragma unroll
    for (int j = 0; j < 32; j += 8)
        t[ty + j][tx] = S[(size_t)(y0 + ty + j) * 512 + x0 + tx];
    __syncthreads();
    uint16_t* Hb = H + (size_t)b * MAT;
    uint16_t* Lb = L + (size_t)b * MAT;
#pragma unroll
    for (int j = 0; j < 32; j += 8) {
        float v = t[tx][ty + j];
        float h = bf16rt(v);
        const size_t idx = (size_t)(x0 + ty + j) * 512 + y0 + tx;
        __nv_bfloat16 hb = __float2bfloat16(v);
        __nv_bfloat16 lb = __float2bfloat16(v - h);
        Hb[idx] = *reinterpret_cast<uint16_t*>(&hb);
        Lb[idx] = *reinterpret_cast<uint16_t*>(&lb);
    }
}

__global__ void cvt_split(const float* __restrict__ src,
                          uint16_t* __restrict__ H, uint16_t* __restrict__ L)
{
    const size_t i = (size_t)blockIdx.x * blockDim.x + threadIdx.x;
    float4 v = ((const float4*)src)[i];
    uint2 h, l;
    h.x = packbf(v.x, v.y);
    h.y = packbf(v.z, v.w);
    l.x = packbf(v.x - bf16rt(v.x), v.y - bf16rt(v.y));
    l.y = packbf(v.z - bf16rt(v.z), v.w - bf16rt(v.w));
    ((uint2*)H)[i] = h;
    ((uint2*)L)[i] = l;
}

__global__ void zero_stats()
{
    int i = blockIdx.x * blockDim.x + threadIdx.x;
    if (i < 3 * CH) { g_sum[i] = 0.f; g_sq[i] = 0.f; }
}

__global__ void finalize_stats()
{
    int i = blockIdx.x * blockDim.x + threadIdx.x;
    if (i < 3 * CH) {
        const float inv_n = 1.0f / (float)(BATCH * LSEQ);
        float m = g_sum[i] * inv_n;
        float v = g_sq[i] * inv_n - m * m;
        g_mean[i] = m;
        g_rstd[i] = rsqrtf(v + 1e-5f);
    }
}

__global__ void bn_relu_row_split(const float* __restrict__ Y,
                                  const float* __restrict__ gamma,
                                  const float* __restrict__ beta, int statOff,
                                  uint16_t* __restrict__ H, uint16_t* __restrict__ L)
{
    const size_t i = (size_t)blockIdx.x * blockDim.x + threadIdx.x;
    const int c = (int)((i >> 7) & 511);
    const float m  = g_mean[statOff + c];
    const float rs = g_rstd[statOff + c];
    const float sc = rs * gamma[c];
    const float sh = beta[c] - m * sc;
    float4 v = ((const float4*)Y)[i];
    v.x = fmaxf(fmaf(v.x, sc, sh), 0.f);
    v.y = fmaxf(fmaf(v.y, sc, sh), 0.f);
    v.z = fmaxf(fmaf(v.z, sc, sh), 0.f);
    v.w = fmaxf(fmaf(v.w, sc, sh), 0.f);
    uint2 h, l;
    h.x = packbf(v.x, v.y); h.y = packbf(v.z, v.w);
    l.x = packbf(v.x - bf16rt(v.x), v.y - bf16rt(v.y));
    l.y = packbf(v.z - bf16rt(v.z), v.w - bf16rt(v.w));
    ((uint2*)H)[i] = h;
    ((uint2*)L)[i] = l;
}

__global__ void bn_relu_col_split(const float* __restrict__ Y,
                                  const float* __restrict__ gamma,
                                  const float* __restrict__ beta, int statOff,
                                  uint16_t* __restrict__ H, uint16_t* __restrict__ L)
{
    const size_t i = (size_t)blockIdx.x * blockDim.x + threadIdx.x;
    const int c4 = (int)(i & 127);
    const float4 g  = ((const float4*)gamma)[c4];
    const float4 be = ((const float4*)beta)[c4];
    const float4 m  = *(const float4*)(g_mean + statOff + c4 * 4);
    const float4 rs = *(const float4*)(g_rstd + statOff + c4 * 4);
    float4 v = ((const float4*)Y)[i];
    v.x = fmaxf(fmaf(v.x, rs.x * g.x, be.x - m.x * rs.x * g.x), 0.f);
    v.y = fmaxf(fmaf(v.y, rs.y * g.y, be.y - m.y * rs.y * g.y), 0.f);
    v.z = fmaxf(fmaf(v.z, rs.z * g.z, be.z - m.z * rs.z * g.z), 0.f);
    v.w = fmaxf(fmaf(v.w, rs.w * g.w, be.w - m.w * rs.w * g.w), 0.f);
    uint2 h, l;
    h.x = packbf(v.x, v.y); h.y = packbf(v.z, v.w);
    l.x = packbf(v.x - bf16rt(v.x), v.y - bf16rt(v.y));
    l.y = packbf(v.z - bf16rt(v.z), v.w - bf16rt(v.w));
    ((uint2*)H)[i] = h;
    ((uint2*)L)[i] = l;
}

__global__ void softmax_split(const float* __restrict__ W,
                              uint16_t* __restrict__ H, uint16_t* __restrict__ L)
{
    const int cd = blockIdx.x * blockDim.x + threadIdx.x;
    float v[BATCH];
    float mx = -3.402823e38f;
#pragma unroll
    for (int b = 0; b < BATCH; b++) {
        v[b] = W[(size_t)b * MAT + cd];
        mx = fmaxf(mx, v[b]);
    }
    float s = 0.f;
#pragma unroll
    for (int b = 0; b < BATCH; b++) { v[b] = expf(v[b] - mx); s += v[b]; }
    const float r = 1.0f / s;
#pragma unroll
    for (int b = 0; b < BATCH; b++) {
        const float z = v[b] * r;
        const float h = bf16rt(z);
        __nv_bfloat16 hb = __float2bfloat16(z);
        __nv_bfloat16 lb = __float2bfloat16(z - h);
        H[(size_t)b * MAT + cd] = *reinterpret_cast<uint16_t*>(&hb);
        L[(size_t)b * MAT + cd] = *reinterpret_cast<uint16_t*>(&lb);
    }
}

// ---------------- orchestration -------------------------------------------------
extern "C" void kernel_launch(void* const* d_in, const int* /*in_sizes*/, int /*n_in*/,
                              void* d_out, int /*out_size*/)
{
    const float* P     = (const float*)d_in[0];
    const float* Wq    = (const float*)d_in[1];
    const float* bq    = (const float*)d_in[2];
    const float* gq    = (const float*)d_in[3];
    const float* betaq = (const float*)d_in[4];
    const float* Wk    = (const float*)d_in[5];
    const float* bk    = (const float*)d_in[6];
    const float* gk    = (const float*)d_in[7];
    const float* betak = (const float*)d_in[8];
    const float* Wv    = (const float*)d_in[9];
    const float* bv    = (const float*)d_in[10];
    const float* gv    = (const float*)d_in[11];
    const float* betav = (const float*)d_in[12];

    cudaFuncSetAttribute(gemm_bf3<0>, cudaFuncAttributeMaxDynamicSharedMemorySize, SMEM_DYN);
    cudaFuncSetAttribute(gemm_bf3<1>, cudaFuncAttributeMaxDynamicSharedMemorySize, SMEM_DYN);
    cudaFuncSetAttribute(gemm_bf3<2>, cudaFuncAttributeMaxDynamicSharedMemorySize, SMEM_DYN);
    cudaFuncSetAttribute(gemm_bf3<3>, cudaFuncAttributeMaxDynamicSharedMemorySize, SMEM_DYN);

    float *Y, *Wsc, *sum, *sq;
    uint16_t *bf, *wth, *wtl;
    cudaGetSymbolAddress((void**)&Y,   g_Y);
    cudaGetSymbolAddress((void**)&Wsc, g_Wsc);
    cudaGetSymbolAddress((void**)&bf,  g_bf);
    cudaGetSymbolAddress((void**)&wth, g_wth);
    cudaGetSymbolAddress((void**)&wtl, g_wtl);
    cudaGetSymbolAddress((void**)&sum, g_sum);
    cudaGetSymbolAddress((void**)&sq,  g_sq);

    uint16_t* QH  = bf;
    uint16_t* QL  = bf + 1ULL * NMAT;
    uint16_t* KH  = bf + 2ULL * NMAT;
    uint16_t* KL  = bf + 3ULL * NMAT;
    uint16_t* VH  = bf + 4ULL * NMAT;
    uint16_t* VL  = bf + 5ULL * NMAT;
    uint16_t* WH  = bf + 6ULL * NMAT;
    uint16_t* WL  = bf + 7ULL * NMAT;
    uint16_t* X0H = bf + 8ULL * NMAT;
    uint16_t* X0L = bf + 9ULL * NMAT;
    uint16_t* X1H = bf + 10ULL * NMAT;
    uint16_t* X1L = bf + 11ULL * NMAT;

    float* Yq = Y;
    float* Yk = Y + 1ULL * NMAT;
    float* Yv = Y + 2ULL * NMAT;

    const dim3 gg(4, 4, BATCH);

    cvt_split<<<3 * MAT / 4 / 256, 256>>>(Wq, wth + 0ULL * 3 * MAT, wtl + 0ULL * 3 * MAT);
    cvt_split<<<3 * MAT / 4 / 256, 256>>>(Wk, wth + 1ULL * 3 * MAT, wtl + 1ULL * 3 * MAT);
    cvt_split<<<3 * MAT / 4 / 256, 256>>>(Wv, wth + 2ULL * 3 * MAT, wtl + 2ULL * 3 * MAT);

    transpose_split<<<dim3(16, 16, BATCH), dim3(32, 8)>>>(P, X0H, X0L);

    for (int d = 0; d < 3; d++) {
        uint16_t* XiH = (d == 1) ? X1H : X0H;
        uint16_t* XiL = (d == 1) ? X1L : X0L;
        uint16_t* XoH = (d == 0) ? X1H : X0H;
        uint16_t* XoL = (d == 0) ? X1L : X0L;

        const uint16_t* wqh = wth + (0ULL * 3 + d) * MAT;
        const uint16_t* wql = wtl + (0ULL * 3 + d) * MAT;
        const uint16_t* wkh = wth + (1ULL * 3 + d) * MAT;
        const uint16_t* wkl = wtl + (1ULL * 3 + d) * MAT;
        const uint16_t* wvh = wth + (2ULL * 3 + d) * MAT;
        const uint16_t* wvl = wtl + (2ULL * 3 + d) * MAT;

        zero_stats<<<6, 256>>>();

        gemm_bf3<1><<<gg, 128, SMEM_DYN>>>(wqh, wql, 0, XiH, XiL, MAT,
                                           Yq, nullptr, nullptr, bq + d * CH, sum, sq);
        gemm_bf3<1><<<gg, 128, SMEM_DYN>>>(wkh, wkl, 0, XiH, XiL, MAT,
                                           Yk, nullptr, nullptr, bk + d * CH, sum + CH, sq + CH);
        gemm_bf3<2><<<gg, 128, SMEM_DYN>>>(XiH, XiL, MAT, wvh, wvl, 0,
                                           Yv, nullptr, nullptr, bv + d * CH, sum + 2 * CH, sq + 2 * CH);

        finalize_stats<<<6, 256>>>();

        bn_relu_row_split<<<NMAT / 4 / 256, 256>>>(Yq, gq + d * CH, betaq + d * CH, 0,      QH, QL);
        bn_relu_row_split<<<NMAT / 4 / 256, 256>>>(Yk, gk + d * CH, betak + d * CH, CH,     KH, KL);
        bn_relu_col_split<<<NMAT / 4 / 256, 256>>>(Yv, gv + d * CH, betav + d * CH, 2 * CH, VH, VL);

        gemm_bf3<0><<<gg, 128, SMEM_DYN>>>(QH, QL, MAT, KH, KL, MAT,
                                           Wsc, nullptr, nullptr, nullptr, nullptr, nullptr);

        softmax_split<<<MAT / 256, 256>>>(Wsc, WH, WL);

        if (d < 2) {
            gemm_bf3<3><<<gg, 128, SMEM_DYN>>>(VH, VL, MAT, WH, WL, MAT,
                                               nullptr, XoH, XoL, nullptr, nullptr, nullptr);
        } else {
            gemm_bf3<0><<<gg, 128, SMEM_DYN>>>(WH, WL, MAT, VH, VL, MAT,
                                               (float*)d_out, nullptr, nullptr, nullptr, nullptr, nullptr);
        }
    }
}

// round 7
// speedup vs baseline: 1.0220x; 1.0220x over previous
#include <cuda_runtime.h>
#include <cuda_bf16.h>
#include <cstdint>
#include <cstddef>

#define BATCH 64
#define CH    512
#define LSEQ  512
#define MAT   (CH * LSEQ)
#define NMAT  (BATCH * MAT)

// ---------------- scratch -----------------------------------------------------
__device__ float    g_Y[3ULL * NMAT];        // Q,K,VT pre-BN fp32
__device__ float    g_Wsc[NMAT];             // scores fp32
__device__ uint16_t g_bf[12ULL * NMAT];      // QH,QL,KH,KL,VH,VL,WH,WL,X0H,X0L,X1H,X1L
__device__ uint16_t g_wth[9ULL * MAT];
__device__ uint16_t g_wtl[9ULL * MAT];
__device__ float g_sum[3 * CH];
__device__ float g_sq[3 * CH];
__device__ float g_mean[3 * CH];
__device__ float g_rstd[3 * CH];

// ---------------- helpers ------------------------------------------------------
__device__ __forceinline__ uint32_t packbf(float a, float b) {
    __nv_bfloat162 t = __floats2bfloat162_rn(a, b);
    return *reinterpret_cast<uint32_t*>(&t);
}
__device__ __forceinline__ float bf16rt(float x) {
    return __bfloat162float(__float2bfloat16(x));
}

#define LDSM4(R, addr) \
    asm volatile("ldmatrix.sync.aligned.m8n8.x4.shared.b16 {%0,%1,%2,%3}, [%4];" \
        : "=r"((R)[0]), "=r"((R)[1]), "=r"((R)[2]), "=r"((R)[3]) : "r"(addr))

__device__ __forceinline__ void mma16816(float* d, const uint32_t* a,
                                         uint32_t b0, uint32_t b1) {
    asm volatile(
        "mma.sync.aligned.m16n8k16.row.col.f32.bf16.bf16.f32 "
        "{%0,%1,%2,%3}, {%4,%5,%6,%7}, {%8,%9}, {%0,%1,%2,%3};"
        : "+f"(d[0]), "+f"(d[1]), "+f"(d[2]), "+f"(d[3])
        : "r"(a[0]), "r"(a[1]), "r"(a[2]), "r"(a[3]), "r"(b0), "r"(b1));
}

#define CP16(dst, src) \
    asm volatile("cp.async.cg.shared.global [%0], [%1], 16;" :: "r"(dst), "l"(src))
#define CPCOMMIT() asm volatile("cp.async.commit_group;" ::: "memory")
#define CPWAIT1()  asm volatile("cp.async.wait_group 1;" ::: "memory")

// ---------------- GEMM core (NT, bf16x3, pre-split operands) -------------------
// D[m][n] = sum_k A[m][k]*B[n][k], 512^3, A/B as bf16 hi+lo (pre-offset ptrs).
// CTA tile 128x128, 4 warps of 64x64, K-chunk 32, 3-stage cp.async pipeline.
// outMode: 0=fp32, 1=fp32+bias+rowstats, 2=fp32+bias+colstats, 3=bf16 hi/lo.
#define KC 32
#define TILE_B  8192                     // 128 rows x 64 B
#define STAGE_B 32768                    // 4 tiles
#define SMEM_DYN (3 * STAGE_B)           // 98304

__device__ __forceinline__ void gemm_core(
    const uint16_t* __restrict__ Ah, const uint16_t* __restrict__ Al,
    const uint16_t* __restrict__ Bh, const uint16_t* __restrict__ Bl,
    float* __restrict__ CfB, uint16_t* __restrict__ ChB, uint16_t* __restrict__ ClB,
    const float* __restrict__ bias,
    float* __restrict__ sums, float* __restrict__ sqs,
    int m0, int n0, int outMode)
{
    extern __shared__ uint8_t smraw[];
    const uint32_t smemu = (uint32_t)__cvta_generic_to_shared(smraw);
    const int tid  = threadIdx.x;
    const int lane = tid & 31, wid = tid >> 5;

    // ---- loader
    const int r0 = tid >> 2, k0 = tid & 3;
    const uint32_t dst0 = (uint32_t)(r0 * 64 + ((k0 ^ ((r0 >> 1) & 3)) << 4));
    const char* aH0 = (const char*)(Ah + (size_t)(m0 + r0) * 512 + k0 * 8);
    const char* aL0 = (const char*)(Al + (size_t)(m0 + r0) * 512 + k0 * 8);
    const char* bH0 = (const char*)(Bh + (size_t)(n0 + r0) * 512 + k0 * 8);
    const char* bL0 = (const char*)(Bl + (size_t)(n0 + r0) * 512 + k0 * 8);

    auto issue = [&](int s, int c) {
        const uint32_t sb = smemu + (uint32_t)s * STAGE_B;
        const size_t o = (size_t)c * (KC * 2);
#pragma unroll
        for (int p = 0; p < 4; p++) {
            const uint32_t d = sb + dst0 + p * 2048;
            const size_t so = o + (size_t)p * 32768;
            CP16(d,              aH0 + so);
            CP16(d + TILE_B,     aL0 + so);
            CP16(d + 2 * TILE_B, bH0 + so);
            CP16(d + 3 * TILE_B, bL0 + so);
        }
    };

    // ---- ldmatrix offsets
    const int mw = (wid & 1) * 64;
    const int nw = (wid >> 1) * 64;
    const int lrow = (lane & 7) + 8 * ((lane >> 3) & 1);
    const int lk16 = lane >> 4;
    uint32_t offA[4][2], offB[4][2];
#pragma unroll
    for (int fi = 0; fi < 4; fi++) {
        const int row = mw + fi * 16 + lrow;
        const uint32_t sw = (row >> 1) & 3;
        offA[fi][0] = (uint32_t)(row * 64 + (((0 + lk16) ^ sw) << 4));
        offA[fi][1] = (uint32_t)(row * 64 + (((2 + lk16) ^ sw) << 4));
    }
#pragma unroll
    for (int bj = 0; bj < 4; bj++) {
        const int row = nw + bj * 16 + lrow;
        const uint32_t sw = (row >> 1) & 3;
        offB[bj][0] = (uint32_t)(row * 64 + (((0 + lk16) ^ sw) << 4));
        offB[bj][1] = (uint32_t)(row * 64 + (((2 + lk16) ^ sw) << 4));
    }

    float acc[4][8][4];
#pragma unroll
    for (int i = 0; i < 4; i++)
#pragma unroll
        for (int j = 0; j < 8; j++)
#pragma unroll
            for (int e = 0; e < 4; e++) acc[i][j][e] = 0.f;

    auto compute = [&](int s) {
        const uint32_t sb = smemu + (uint32_t)s * STAGE_B;
#pragma unroll
        for (int kg = 0; kg < 2; kg++) {
            uint32_t Ahr[4][4], Bhr[4][4], Blr[4][4], Alr[4][4];
#pragma unroll
            for (int fi = 0; fi < 4; fi++)
                LDSM4(Ahr[fi], sb + offA[fi][kg]);
#pragma unroll
            for (int bj = 0; bj < 4; bj++)
                LDSM4(Bhr[bj], sb + 2 * TILE_B + offB[bj][kg]);
#pragma unroll
            for (int i = 0; i < 4; i++)
#pragma unroll
                for (int j = 0; j < 8; j++)
                    mma16816(acc[i][j], Ahr[i], Bhr[j >> 1][j & 1], Bhr[j >> 1][(j & 1) + 2]);
#pragma unroll
            for (int bj = 0; bj < 4; bj++)
                LDSM4(Blr[bj], sb + 3 * TILE_B + offB[bj][kg]);
#pragma unroll
            for (int i = 0; i < 4; i++)
#pragma unroll
                for (int j = 0; j < 8; j++)
                    mma16816(acc[i][j], Ahr[i], Blr[j >> 1][j & 1], Blr[j >> 1][(j & 1) + 2]);
#pragma unroll
            for (int fi = 0; fi < 4; fi++)
                LDSM4(Alr[fi], sb + TILE_B + offA[fi][kg]);
#pragma unroll
            for (int i = 0; i < 4; i++)
#pragma unroll
                for (int j = 0; j < 8; j++)
                    mma16816(acc[i][j], Alr[i], Bhr[j >> 1][j & 1], Bhr[j >> 1][(j & 1) + 2]);
        }
    };

    issue(0, 0); CPCOMMIT();
    issue(1, 1); CPCOMMIT();

#pragma unroll 1
    for (int c = 0; c < 16; c++) {
        CPWAIT1();
        __syncthreads();
        if (c + 2 < 16) issue((c + 2) % 3, c + 2);
        CPCOMMIT();
        compute(c % 3);
    }

    // ---------------- epilogue ----------------
    const int rg = lane >> 2;
    const int cg = (lane & 3) * 2;

    float bc[16], cs[16], cq[16];
    if (outMode == 2) {
#pragma unroll
        for (int j = 0; j < 8; j++) {
            bc[2 * j]     = bias[n0 + nw + j * 8 + cg];
            bc[2 * j + 1] = bias[n0 + nw + j * 8 + cg + 1];
        }
#pragma unroll
        for (int e = 0; e < 16; e++) { cs[e] = 0.f; cq[e] = 0.f; }
    }

#pragma unroll
    for (int i = 0; i < 4; i++) {
        const int row0 = m0 + mw + i * 16 + rg;
        const int row1 = row0 + 8;
        float bv0 = 0.f, bv1 = 0.f;
        if (outMode == 1) { bv0 = bias[row0]; bv1 = bias[row1]; }
        float s0 = 0.f, q0 = 0.f, s1 = 0.f, q1 = 0.f;
#pragma unroll
        for (int j = 0; j < 8; j++) {
            float* cc = acc[i][j];
            if (outMode == 1) { cc[0] += bv0; cc[1] += bv0; cc[2] += bv1; cc[3] += bv1; }
            if (outMode == 2) {
                cc[0] += bc[2 * j]; cc[1] += bc[2 * j + 1];
                cc[2] += bc[2 * j]; cc[3] += bc[2 * j + 1];
            }
            const int col = n0 + nw + j * 8 + cg;
            if (outMode == 3) {
                uint32_t* H = (uint32_t*)ChB;
                uint32_t* L = (uint32_t*)ClB;
                const size_t i0 = ((size_t)row0 * 512 + col) >> 1;
                const size_t i1 = ((size_t)row1 * 512 + col) >> 1;
                H[i0] = packbf(cc[0], cc[1]);
                L[i0] = packbf(cc[0] - bf16rt(cc[0]), cc[1] - bf16rt(cc[1]));
                H[i1] = packbf(cc[2], cc[3]);
                L[i1] = packbf(cc[2] - bf16rt(cc[2]), cc[3] - bf16rt(cc[3]));
            } else {
                *(float2*)&CfB[(size_t)row0 * 512 + col] = make_float2(cc[0], cc[1]);
                *(float2*)&CfB[(size_t)row1 * 512 + col] = make_float2(cc[2], cc[3]);
            }
            if (outMode == 1) {
                s0 += cc[0] + cc[1]; q0 += cc[0] * cc[0] + cc[1] * cc[1];
                s1 += cc[2] + cc[3]; q1 += cc[2] * cc[2] + cc[3] * cc[3];
            }
            if (outMode == 2) {
                cs[2 * j]     += cc[0] + cc[2];
                cs[2 * j + 1] += cc[1] + cc[3];
                cq[2 * j]     += cc[0] * cc[0] + cc[2] * cc[2];
                cq[2 * j + 1] += cc[1] * cc[1] + cc[3] * cc[3];
            }
        }
        if (outMode == 1) {
#pragma unroll
            for (int off = 1; off <= 2; off <<= 1) {
                s0 += __shfl_xor_sync(0xffffffffu, s0, off);
                q0 += __shfl_xor_sync(0xffffffffu, q0, off);
                s1 += __shfl_xor_sync(0xffffffffu, s1, off);
                q1 += __shfl_xor_sync(0xffffffffu, q1, off);
            }
            if ((lane & 3) == 0) {
                atomicAdd(&sums[row0], s0); atomicAdd(&sqs[row0], q0);
                atomicAdd(&sums[row1], s1); atomicAdd(&sqs[row1], q1);
            }
        }
    }
    if (outMode == 2) {
#pragma unroll
        for (int e = 0; e < 16; e++) {
#pragma unroll
            for (int off = 4; off <= 16; off <<= 1) {
                cs[e] += __shfl_xor_sync(0xffffffffu, cs[e], off);
                cq[e] += __shfl_xor_sync(0xffffffffu, cq[e], off);
            }
        }
        if (rg == 0) {
#pragma unroll
            for (int j = 0; j < 8; j++) {
                const int col = n0 + nw + j * 8 + cg;
                atomicAdd(&sums[col], cs[2 * j]);         atomicAdd(&sqs[col], cq[2 * j]);
                atomicAdd(&sums[col + 1], cs[2 * j + 1]); atomicAdd(&sqs[col + 1], cq[2 * j + 1]);
            }
        }
    }
}

// standalone GEMM (scores / AV)
__global__ __launch_bounds__(128, 2) void gemm_bf3(
    const uint16_t* __restrict__ Ah, const uint16_t* __restrict__ Al, int strideA,
    const uint16_t* __restrict__ Bh, const uint16_t* __restrict__ Bl, int strideB,
    float* __restrict__ Cf,
    uint16_t* __restrict__ Ch, uint16_t* __restrict__ Cl,
    int outMode)
{
    const int b = blockIdx.z;
    gemm_core(Ah + (size_t)b * strideA, Al + (size_t)b * strideA,
              Bh + (size_t)b * strideB, Bl + (size_t)b * strideB,
              Cf ? Cf + (size_t)b * MAT : nullptr,
              Ch ? Ch + (size_t)b * MAT : nullptr,
              Cl ? Cl + (size_t)b * MAT : nullptr,
              nullptr, nullptr, nullptr,
              blockIdx.y * 128, blockIdx.x * 128, outMode);
}

// fused 3-projection GEMM: z in [0,192), proj = z>>6, batch = z&63
__global__ __launch_bounds__(128, 2) void proj3_gemm(
    const uint16_t* __restrict__ wqh, const uint16_t* __restrict__ wql,
    const uint16_t* __restrict__ wkh, const uint16_t* __restrict__ wkl,
    const uint16_t* __restrict__ wvh, const uint16_t* __restrict__ wvl,
    const uint16_t* __restrict__ XiH, const uint16_t* __restrict__ XiL,
    float* __restrict__ Yq, float* __restrict__ Yk, float* __restrict__ Yv,
    const float* __restrict__ bq, const float* __restrict__ bk, const float* __restrict__ bv,
    float* __restrict__ sum, float* __restrict__ sq)
{
    const int proj = blockIdx.z >> 6;
    const int b    = blockIdx.z & 63;
    const size_t xo = (size_t)b * MAT;

    const uint16_t *Ah, *Al, *Bh, *Bl;
    float* Cf;
    const float* bias;
    float *sums, *sqs;
    int mode;
    if (proj == 0) {
        Ah = wqh; Al = wql; Bh = XiH + xo; Bl = XiL + xo;
        Cf = Yq + xo; bias = bq; sums = sum; sqs = sq; mode = 1;
    } else if (proj == 1) {
        Ah = wkh; Al = wkl; Bh = XiH + xo; Bl = XiL + xo;
        Cf = Yk + xo; bias = bk; sums = sum + CH; sqs = sq + CH; mode = 1;
    } else {
        Ah = XiH + xo; Al = XiL + xo; Bh = wvh; Bl = wvl;
        Cf = Yv + xo; bias = bv; sums = sum + 2 * CH; sqs = sq + 2 * CH; mode = 2;
    }
    gemm_core(Ah, Al, Bh, Bl, Cf, nullptr, nullptr, bias, sums, sqs,
              blockIdx.y * 128, blockIdx.x * 128, mode);
}

// ---------------- elementwise kernels -------------------------------------------
__global__ void transpose_split(const float* __restrict__ src,
                                uint16_t* __restrict__ H, uint16_t* __restrict__ L)
{
    __shared__ float t[32][33];
    const int b = blockIdx.z;
    const int x0 = blockIdx.x * 32;
    const int y0 = blockIdx.y * 32;
    const float* S = src + (size_t)b * MAT;
    const int tx = threadIdx.x, ty = threadIdx.y;
#pragma unroll
    for (int j = 0; j < 32; j += 8)
        t[ty + j][tx] = S[(size_t)(y0 + ty + j) * 512 + x0 + tx];
    __syncthreads();
    uint16_t* Hb = H + (size_t)b * MAT;
    uint16_t* Lb = L + (size_t)b * MAT;
#pragma unroll
    for (int j = 0; j < 32; j += 8) {
        float v = t[tx][ty + j];
        float h = bf16rt(v);
        const size_t idx = (size_t)(x0 + ty + j) * 512 + y0 + tx;
        __nv_bfloat16 hb = __float2bfloat16(v);
        __nv_bfloat16 lb = __float2bfloat16(v - h);
        Hb[idx] = *reinterpret_cast<uint16_t*>(&hb);
        Lb[idx] = *reinterpret_cast<uint16_t*>(&lb);
    }
}

__global__ void cvt_split(const float* __restrict__ src,
                          uint16_t* __restrict__ H, uint16_t* __restrict__ L)
{
    const size_t i = (size_t)blockIdx.x * blockDim.x + threadIdx.x;
    float4 v = ((const float4*)src)[i];
    uint2 h, l;
    h.x = packbf(v.x, v.y);
    h.y = packbf(v.z, v.w);
    l.x = packbf(v.x - bf16rt(v.x), v.y - bf16rt(v.y));
    l.y = packbf(v.z - bf16rt(v.z), v.w - bf16rt(v.w));
    ((uint2*)H)[i] = h;
    ((uint2*)L)[i] = l;
}

__global__ void zero_stats()
{
    int i = blockIdx.x * blockDim.x + threadIdx.x;
    if (i < 3 * CH) { g_sum[i] = 0.f; g_sq[i] = 0.f; }
}

__global__ void finalize_stats()
{
    int i = blockIdx.x * blockDim.x + threadIdx.x;
    if (i < 3 * CH) {
        const float inv_n = 1.0f / (float)(BATCH * LSEQ);
        float m = g_sum[i] * inv_n;
        float v = g_sq[i] * inv_n - m * m;
        g_mean[i] = m;
        g_rstd[i] = rsqrtf(v + 1e-5f);
    }
}

// fused BN+ReLU+split for Q (row), K (row), V (col) — selected by blockIdx.y
__global__ void bn3_split(
    const float* __restrict__ Yq, const float* __restrict__ Yk, const float* __restrict__ Yv,
    const float* __restrict__ gq, const float* __restrict__ betaq,
    const float* __restrict__ gk, const float* __restrict__ betak,
    const float* __restrict__ gv, const float* __restrict__ betav,
    uint16_t* __restrict__ QH, uint16_t* __restrict__ QL,
    uint16_t* __restrict__ KH, uint16_t* __restrict__ KL,
    uint16_t* __restrict__ VH, uint16_t* __restrict__ VL)
{
    const size_t i = (size_t)blockIdx.x * blockDim.x + threadIdx.x;
    const int which = blockIdx.y;
    float4 v;
    uint16_t *H, *L;
    if (which < 2) {
        const float* Y = (which == 0) ? Yq : Yk;
        const float* g = (which == 0) ? gq : gk;
        const float* be = (which == 0) ? betaq : betak;
        const int so = which * CH;
        const int c = (int)((i >> 7) & 511);
        const float m  = g_mean[so + c];
        const float rs = g_rstd[so + c];
        const float sc = rs * g[c];
        const float sh = be[c] - m * sc;
        v = ((const float4*)Y)[i];
        v.x = fmaxf(fmaf(v.x, sc, sh), 0.f);
        v.y = fmaxf(fmaf(v.y, sc, sh), 0.f);
        v.z = fmaxf(fmaf(v.z, sc, sh), 0.f);
        v.w = fmaxf(fmaf(v.w, sc, sh), 0.f);
        H = (which == 0) ? QH : KH;
        L = (which == 0) ? QL : KL;
    } else {
        const int c4 = (int)(i & 127);
        const float4 g  = ((const float4*)gv)[c4];
        const float4 be = ((const float4*)betav)[c4];
        const float4 m  = *(const float4*)(g_mean + 2 * CH + c4 * 4);
        const float4 rs = *(const float4*)(g_rstd + 2 * CH + c4 * 4);
        v = ((const float4*)Yv)[i];
        v.x = fmaxf(fmaf(v.x, rs.x * g.x, be.x - m.x * rs.x * g.x), 0.f);
        v.y = fmaxf(fmaf(v.y, rs.y * g.y, be.y - m.y * rs.y * g.y), 0.f);
        v.z = fmaxf(fmaf(v.z, rs.z * g.z, be.z - m.z * rs.z * g.z), 0.f);
        v.w = fmaxf(fmaf(v.w, rs.w * g.w, be.w - m.w * rs.w * g.w), 0.f);
        H = VH; L = VL;
    }
    uint2 h, l;
    h.x = packbf(v.x, v.y); h.y = packbf(v.z, v.w);
    l.x = packbf(v.x - bf16rt(v.x), v.y - bf16rt(v.y));
    l.y = packbf(v.z - bf16rt(v.z), v.w - bf16rt(v.w));
    ((uint2*)H)[i] = h;
    ((uint2*)L)[i] = l;
}

__global__ void softmax_split(const float* __restrict__ W,
                              uint16_t* __restrict__ H, uint16_t* __restrict__ L)
{
    const int cd = blockIdx.x * blockDim.x + threadIdx.x;
    float v[BATCH];
    float mx = -3.402823e38f;
#pragma unroll
    for (int b = 0; b < BATCH; b++) {
        v[b] = W[(size_t)b * MAT + cd];
        mx = fmaxf(mx, v[b]);
    }
    float s = 0.f;
#pragma unroll
    for (int b = 0; b < BATCH; b++) { v[b] = __expf(v[b] - mx); s += v[b]; }
    const float r = 1.0f / s;
#pragma unroll
    for (int b = 0; b < BATCH; b++) {
        const float z = v[b] * r;
        const float h = bf16rt(z);
        __nv_bfloat16 hb = __float2bfloat16(z);
        __nv_bfloat16 lb = __float2bfloat16(z - h);
        H[(size_t)b * MAT + cd] = *reinterpret_cast<uint16_t*>(&hb);
        L[(size_t)b * MAT + cd] = *reinterpret_cast<uint16_t*>(&lb);
    }
}

// ---------------- orchestration -------------------------------------------------
extern "C" void kernel_launch(void* const* d_in, const int* /*in_sizes*/, int /*n_in*/,
                              void* d_out, int /*out_size*/)
{
    const float* P     = (const float*)d_in[0];
    const float* Wq    = (const float*)d_in[1];
    const float* bq    = (const float*)d_in[2];
    const float* gq    = (const float*)d_in[3];
    const float* betaq = (const float*)d_in[4];
    const float* Wk    = (const float*)d_in[5];
    const float* bk    = (const float*)d_in[6];
    const float* gk    = (const float*)d_in[7];
    const float* betak = (const float*)d_in[8];
    const float* Wv    = (const float*)d_in[9];
    const float* bv    = (const float*)d_in[10];
    const float* gv    = (const float*)d_in[11];
    const float* betav = (const float*)d_in[12];

    cudaFuncSetAttribute(gemm_bf3,   cudaFuncAttributeMaxDynamicSharedMemorySize, SMEM_DYN);
    cudaFuncSetAttribute(proj3_gemm, cudaFuncAttributeMaxDynamicSharedMemorySize, SMEM_DYN);

    float *Y, *Wsc, *sum, *sq;
    uint16_t *bf, *wth, *wtl;
    cudaGetSymbolAddress((void**)&Y,   g_Y);
    cudaGetSymbolAddress((void**)&Wsc, g_Wsc);
    cudaGetSymbolAddress((void**)&bf,  g_bf);
    cudaGetSymbolAddress((void**)&wth, g_wth);
    cudaGetSymbolAddress((void**)&wtl, g_wtl);
    cudaGetSymbolAddress((void**)&sum, g_sum);
    cudaGetSymbolAddress((void**)&sq,  g_sq);

    uint16_t* QH  = bf;
    uint16_t* QL  = bf + 1ULL * NMAT;
    uint16_t* KH  = bf + 2ULL * NMAT;
    uint16_t* KL  = bf + 3ULL * NMAT;
    uint16_t* VH  = bf + 4ULL * NMAT;
    uint16_t* VL  = bf + 5ULL * NMAT;
    uint16_t* WH  = bf + 6ULL * NMAT;
    uint16_t* WL  = bf + 7ULL * NMAT;
    uint16_t* X0H = bf + 8ULL * NMAT;
    uint16_t* X0L = bf + 9ULL * NMAT;
    uint16_t* X1H = bf + 10ULL * NMAT;
    uint16_t* X1L = bf + 11ULL * NMAT;

    float* Yq = Y;
    float* Yk = Y + 1ULL * NMAT;
    float* Yv = Y + 2ULL * NMAT;

    cvt_split<<<3 * MAT / 4 / 256, 256>>>(Wq, wth + 0ULL * 3 * MAT, wtl + 0ULL * 3 * MAT);
    cvt_split<<<3 * MAT / 4 / 256, 256>>>(Wk, wth + 1ULL * 3 * MAT, wtl + 1ULL * 3 * MAT);
    cvt_split<<<3 * MAT / 4 / 256, 256>>>(Wv, wth + 2ULL * 3 * MAT, wtl + 2ULL * 3 * MAT);

    transpose_split<<<dim3(16, 16, BATCH), dim3(32, 8)>>>(P, X0H, X0L);

    for (int d = 0; d < 3; d++) {
        uint16_t* XiH = (d == 1) ? X1H : X0H;
        uint16_t* XiL = (d == 1) ? X1L : X0L;
        uint16_t* XoH = (d == 0) ? X1H : X0H;
        uint16_t* XoL = (d == 0) ? X1L : X0L;

        const uint16_t* wqh = wth + (0ULL * 3 + d) * MAT;
        const uint16_t* wql = wtl + (0ULL * 3 + d) * MAT;
        const uint16_t* wkh = wth + (1ULL * 3 + d) * MAT;
        const uint16_t* wkl = wtl + (1ULL * 3 + d) * MAT;
        const uint16_t* wvh = wth + (2ULL * 3 + d) * MAT;
        const uint16_t* wvl = wtl + (2ULL * 3 + d) * MAT;

        zero_stats<<<6, 256>>>();

        proj3_gemm<<<dim3(4, 4, 3 * BATCH), 128, SMEM_DYN>>>(
            wqh, wql, wkh, wkl, wvh, wvl, XiH, XiL,
            Yq, Yk, Yv, bq + d * CH, bk + d * CH, bv + d * CH, sum, sq);

        finalize_stats<<<6, 256>>>();

        bn3_split<<<dim3(NMAT / 4 / 256, 3), 256>>>(
            Yq, Yk, Yv,
            gq + d * CH, betaq + d * CH,
            gk + d * CH, betak + d * CH,
            gv + d * CH, betav + d * CH,
            QH, QL, KH, KL, VH, VL);

        // scores w[c][d'] = Q x K (NT over l)
        gemm_bf3<<<dim3(4, 4, BATCH), 128, SMEM_DYN>>>(QH, QL, MAT, KH, KL, MAT,
                                                       Wsc, nullptr, nullptr, 0);

        softmax_split<<<MAT / 256, 256>>>(Wsc, WH, WL);

        if (d < 2) {
            gemm_bf3<<<dim3(4, 4, BATCH), 128, SMEM_DYN>>>(VH, VL, MAT, WH, WL, MAT,
                                                           nullptr, XoH, XoL, 3);
        } else {
            gemm_bf3<<<dim3(4, 4, BATCH), 128, SMEM_DYN>>>(WH, WL, MAT, VH, VL, MAT,
                                                           (float*)d_out, nullptr, nullptr, 0);
        }
    }
}